// round 2
// baseline (speedup 1.0000x reference)
#include <cuda_runtime.h>
#include <math_constants.h>
#include <stdint.h>

// Problem constants
#define B_    8
#define A_    400
#define R_    1024
#define M_    4096
#define MC    6             // map_pc columns: x,y,z,nx,ny,nz
#define KPK   4
#define NPTS  (A_*KPK)      // 1600 scan points per batch
#define NIT   50
#define RESF  0.0596f
#define TRIMF 5.0f
#define GRID  64
#define CELLSZ 1.875f       // 120 / 64
#define INVCELL (1.0f/1.875f)
#define XMIN  (-60.0f)

// Scratch (no allocations allowed): extracted scan points + weights
__device__ float g_scanx[B_*NPTS];
__device__ float g_scany[B_*NPTS];
__device__ float g_scanw[B_*NPTS];

// ---------------------------------------------------------------------------
// Kernel 1: BFAR extraction. One warp per (b, a) row.
// score = fft - (relu(a)*mean + relu(b)); top-4 (value desc, tie -> lower idx)
// ---------------------------------------------------------------------------
__global__ void extract_kernel(const float* __restrict__ fft,
                               const float* __restrict__ az,
                               const float* __restrict__ params) {
    int gtid = blockIdx.x * blockDim.x + threadIdx.x;
    int row  = gtid >> 5;
    int lane = gtid & 31;
    if (row >= B_ * A_) return;

    const float* rp = fft + (size_t)row * R_;

    // mean over 1024
    float sum = 0.f;
    #pragma unroll
    for (int i = 0; i < R_/32; ++i) sum += rp[i*32 + lane];
    #pragma unroll
    for (int off = 16; off; off >>= 1) sum += __shfl_xor_sync(0xffffffffu, sum, off);
    float mean = sum * (1.0f / (float)R_);
    float pa = fmaxf(params[0], 0.f);
    float pb = fmaxf(params[1], 0.f);
    float thr = pa * mean + pb;

    // per-lane top-4 of score (sorted desc, stable: equal values keep earlier idx)
    float v0=-CUDART_INF_F, v1=-CUDART_INF_F, v2=-CUDART_INF_F, v3=-CUDART_INF_F;
    int   i0=0x7fffffff,   i1=0x7fffffff,   i2=0x7fffffff,   i3=0x7fffffff;
    #pragma unroll
    for (int i = 0; i < R_/32; ++i) {
        int idx = i*32 + lane;
        float sc = rp[idx] - thr;
        if (sc > v3) {
            v3 = sc; i3 = idx;
            if (v3 > v2) { float tv=v2; v2=v3; v3=tv; int ti=i2; i2=i3; i3=ti; }
            if (v2 > v1) { float tv=v1; v1=v2; v2=tv; int ti=i1; i1=i2; i2=ti; }
            if (v1 > v0) { float tv=v0; v0=v1; v1=tv; int ti=i0; i0=i1; i1=ti; }
        }
    }

    // warp merge: 4 rounds of argmax (tie -> lower index), lane k keeps rank k
    int ptr = 0;
    float outv = 0.f; int outi = 0;
    #pragma unroll
    for (int k = 0; k < KPK; ++k) {
        float cv = (ptr==0) ? v0 : (ptr==1) ? v1 : (ptr==2) ? v2 : (ptr==3) ? v3 : -CUDART_INF_F;
        int   ci = (ptr==0) ? i0 : (ptr==1) ? i1 : (ptr==2) ? i2 : (ptr==3) ? i3 : 0x7fffffff;
        float bv = cv; int bi = ci;
        #pragma unroll
        for (int off = 16; off; off >>= 1) {
            float ov = __shfl_xor_sync(0xffffffffu, bv, off);
            int   oi = __shfl_xor_sync(0xffffffffu, bi, off);
            if (ov > bv || (ov == bv && oi < bi)) { bv = ov; bi = oi; }
        }
        if (bi == ci && ptr < 4) ptr++;
        if (lane == k) { outv = bv; outi = bi; }
    }

    if (lane < KPK) {
        float rng = ((float)outi + 0.5f) * RESF;
        float azv = az[row];
        float x = rng * cosf(azv);
        float y = rng * sinf(azv);
        int o = row * KPK + lane;        // == b*1600 + a*4 + k
        g_scanx[o] = x;
        g_scany[o] = y;
        g_scanw[o] = fmaxf(outv, 0.f);
    }
}

// ---------------------------------------------------------------------------
// Kernel 2: persistent ICP. One CTA (1024 threads) per batch.
// Shared-memory spatial hash grid over the map; 50 GN iterations in-kernel.
// ---------------------------------------------------------------------------
struct IcpSmem {
    float4 smap[M_];               // sorted (x, y, nx, ny)           64 KB
    int    cellStart[GRID*GRID+1]; //                                 16.4 KB
    int    cellOfs[GRID*GRID];     // counts / scatter cursors        16.4 KB
    float  sx[NPTS];
    float  sy[NPTS];
    float  sw[NPTS];               //                                 19.2 KB
    float  red[32][12];            // per-warp partials (padded)
    int    wsum[32];
    float  state[4];               // theta, tx, ty
};

__global__ void __launch_bounds__(1024, 1)
icp_kernel(const float* __restrict__ map_pc,
           const float* __restrict__ T_init,
           float* __restrict__ out) {
    extern __shared__ char smraw[];
    IcpSmem& S = *reinterpret_cast<IcpSmem*>(smraw);

    const int b    = blockIdx.x;
    const int tid  = threadIdx.x;
    const int lane = tid & 31;
    const int wid  = tid >> 5;
    const float* mp = map_pc + (size_t)b * M_ * MC;

    // --- build grid: count ---
    for (int c = tid; c < GRID*GRID; c += 1024) S.cellOfs[c] = 0;
    __syncthreads();
    for (int i = tid; i < M_; i += 1024) {
        float x = mp[i*MC + 0], y = mp[i*MC + 1];
        int gx = min(max((int)floorf((x - XMIN) * INVCELL), 0), GRID-1);
        int gy = min(max((int)floorf((y - XMIN) * INVCELL), 0), GRID-1);
        atomicAdd(&S.cellOfs[gy*GRID + gx], 1);
    }
    __syncthreads();

    // --- exclusive prefix scan over 4096 cells (4 cells / thread) ---
    {
        int t = tid;
        int r0 = S.cellOfs[4*t+0], r1 = S.cellOfs[4*t+1];
        int r2 = S.cellOfs[4*t+2], r3 = S.cellOfs[4*t+3];
        int s = r0 + r1 + r2 + r3;
        int v = s;
        #pragma unroll
        for (int off = 1; off < 32; off <<= 1) {
            int u = __shfl_up_sync(0xffffffffu, v, off);
            if (lane >= off) v += u;
        }
        if (lane == 31) S.wsum[wid] = v;
        __syncthreads();
        if (wid == 0) {
            int wv = S.wsum[lane];
            #pragma unroll
            for (int off = 1; off < 32; off <<= 1) {
                int u = __shfl_up_sync(0xffffffffu, wv, off);
                if (lane >= off) wv += u;
            }
            S.wsum[lane] = wv;
        }
        __syncthreads();
        int base = (v - s) + (wid ? S.wsum[wid-1] : 0);
        S.cellStart[4*t+0] = base;
        S.cellStart[4*t+1] = base + r0;
        S.cellStart[4*t+2] = base + r0 + r1;
        S.cellStart[4*t+3] = base + r0 + r1 + r2;
        if (t == 1023) S.cellStart[GRID*GRID] = base + s;
    }
    __syncthreads();
    for (int c = tid; c < GRID*GRID; c += 1024) S.cellOfs[c] = S.cellStart[c];
    __syncthreads();

    // --- scatter map points (normalize 2D normals) ---
    for (int i = tid; i < M_; i += 1024) {
        float x  = mp[i*MC + 0], y  = mp[i*MC + 1];
        float nx = mp[i*MC + 3], ny = mp[i*MC + 4];
        float nrm = sqrtf(nx*nx + ny*ny);
        float d   = fmaxf(nrm, 1e-12f);
        nx /= d; ny /= d;
        int gx = min(max((int)floorf((x - XMIN) * INVCELL), 0), GRID-1);
        int gy = min(max((int)floorf((y - XMIN) * INVCELL), 0), GRID-1);
        int pos = atomicAdd(&S.cellOfs[gy*GRID + gx], 1);
        S.smap[pos] = make_float4(x, y, nx, ny);
    }

    // --- load scan points, init state ---
    for (int i = tid; i < NPTS; i += 1024) {
        S.sx[i] = g_scanx[b*NPTS + i];
        S.sy[i] = g_scany[b*NPTS + i];
        S.sw[i] = g_scanw[b*NPTS + i];
    }
    if (tid == 0) {
        const float* T = T_init + b*16;
        S.state[0] = atan2f(T[4], T[0]);
        S.state[1] = T[3];
        S.state[2] = T[7];
    }
    __syncthreads();

    // --- 50 GN iterations ---
    for (int it = 0; it < NIT; ++it) {
        float theta = S.state[0], tx = S.state[1], ty = S.state[2];
        float cth = cosf(theta), sth = sinf(theta);

        float a00=0.f,a01=0.f,a02=0.f,a11=0.f,a12=0.f,a22=0.f;
        float g0=0.f,g1=0.f,g2=0.f;

        for (int i = tid; i < NPTS; i += 1024) {
            float sxv = S.sx[i], syv = S.sy[i], wv = S.sw[i];
            float px = cth*sxv - sth*syv + tx;
            float py = sth*sxv + cth*syv + ty;

            int cgx = min(max((int)floorf((px - XMIN) * INVCELL), 0), GRID-1);
            int cgy = min(max((int)floorf((py - XMIN) * INVCELL), 0), GRID-1);

            float bestd2 = 1e30f;
            int   bestk  = -1;

            auto scanSpan = [&](int gy, int xa, int xb) {
                if ((unsigned)gy >= (unsigned)GRID) return;
                xa = max(xa, 0); xb = min(xb, GRID-1);
                if (xa > xb) return;
                int k0 = S.cellStart[gy*GRID + xa];
                int k1 = S.cellStart[gy*GRID + xb + 1];
                for (int k = k0; k < k1; ++k) {
                    float4 m = S.smap[k];
                    float dx = px - m.x, dy = py - m.y;
                    float d2 = dx*dx + dy*dy;
                    if (d2 < bestd2) { bestd2 = d2; bestk = k; }
                }
            };

            for (int r = 0; r < GRID; ++r) {
                if (r >= 1) {
                    float mf = (float)(r-1) * CELLSZ;  // min dist of unprocessed pts
                    if (mf*mf >= bestd2) break;
                    if (mf >= TRIMF && bestd2 >= TRIMF*TRIMF) break;
                }
                int xa = cgx - r, xb = cgx + r;
                int ylo = cgy - r, yhi = cgy + r;
                scanSpan(ylo, xa, xb);
                if (r > 0) {
                    scanSpan(yhi, xa, xb);
                    for (int gy = ylo + 1; gy <= yhi - 1; ++gy) {
                        scanSpan(gy, xa, xa);
                        scanSpan(gy, xb, xb);
                    }
                }
            }

            if (bestk >= 0 && bestd2 < TRIMF*TRIMF) {
                float4 m = S.smap[bestk];
                float res = m.z*(px - m.x) + m.w*(py - m.y);
                float hub = fminf(1.f, 1.f / fmaxf(fabsf(res), 1e-12f));
                float wt  = wv * hub;
                float dr0 = -sth*sxv - cth*syv;
                float dr1 =  cth*sxv - sth*syv;
                float j2  = m.z*dr0 + m.w*dr1;
                a00 += wt*m.z*m.z; a01 += wt*m.z*m.w; a02 += wt*m.z*j2;
                a11 += wt*m.w*m.w; a12 += wt*m.w*j2;  a22 += wt*j2*j2;
                g0  += wt*m.z*res; g1  += wt*m.w*res; g2  += wt*j2*res;
            }
        }

        // warp tree-reduce 9 values
        #pragma unroll
        for (int off = 16; off; off >>= 1) {
            a00 += __shfl_xor_sync(0xffffffffu, a00, off);
            a01 += __shfl_xor_sync(0xffffffffu, a01, off);
            a02 += __shfl_xor_sync(0xffffffffu, a02, off);
            a11 += __shfl_xor_sync(0xffffffffu, a11, off);
            a12 += __shfl_xor_sync(0xffffffffu, a12, off);
            a22 += __shfl_xor_sync(0xffffffffu, a22, off);
            g0  += __shfl_xor_sync(0xffffffffu, g0 , off);
            g1  += __shfl_xor_sync(0xffffffffu, g1 , off);
            g2  += __shfl_xor_sync(0xffffffffu, g2 , off);
        }
        if (lane == 0) {
            S.red[wid][0]=a00; S.red[wid][1]=a01; S.red[wid][2]=a02;
            S.red[wid][3]=a11; S.red[wid][4]=a12; S.red[wid][5]=a22;
            S.red[wid][6]=g0;  S.red[wid][7]=g1;  S.red[wid][8]=g2;
        }
        __syncthreads();

        if (wid == 0) {
            float r9[9];
            #pragma unroll
            for (int k = 0; k < 9; ++k) r9[k] = S.red[lane][k];
            #pragma unroll
            for (int off = 16; off; off >>= 1) {
                #pragma unroll
                for (int k = 0; k < 9; ++k)
                    r9[k] += __shfl_xor_sync(0xffffffffu, r9[k], off);
            }
            if (lane == 0) {
                float A00 = r9[0] + 1e-8f, A01 = r9[1], A02 = r9[2];
                float A11 = r9[3] + 1e-8f, A12 = r9[4], A22 = r9[5] + 1e-8f;
                float G0 = r9[6], G1 = r9[7], G2 = r9[8];
                // Cholesky solve: A dx = -g   (A is SPD)
                float l00 = sqrtf(fmaxf(A00, 1e-30f));
                float l10 = A01 / l00, l20 = A02 / l00;
                float l11 = sqrtf(fmaxf(A11 - l10*l10, 1e-30f));
                float l21 = (A12 - l20*l10) / l11;
                float l22 = sqrtf(fmaxf(A22 - l20*l20 - l21*l21, 1e-30f));
                float y0 = (-G0) / l00;
                float y1 = (-G1 - l10*y0) / l11;
                float y2 = (-G2 - l20*y0 - l21*y1) / l22;
                float x2 = y2 / l22;
                float x1 = (y1 - l21*x2) / l11;
                float x0 = (y0 - l10*x1 - l20*x2) / l00;
                S.state[0] = theta + x2;
                S.state[1] = tx + x0;
                S.state[2] = ty + x1;
            }
        }
        __syncthreads();
    }

    if (tid == 0) {
        float theta = S.state[0], tx = S.state[1], ty = S.state[2];
        float c = cosf(theta), s = sinf(theta);
        float* T = out + b*16;
        T[0]=c;   T[1]=-s;  T[2]=0.f; T[3]=tx;
        T[4]=s;   T[5]=c;   T[6]=0.f; T[7]=ty;
        T[8]=0.f; T[9]=0.f; T[10]=1.f;T[11]=0.f;
        T[12]=0.f;T[13]=0.f;T[14]=0.f;T[15]=1.f;
    }
}

// ---------------------------------------------------------------------------
extern "C" void kernel_launch(void* const* d_in, const int* in_sizes, int n_in,
                              void* d_out, int out_size) {
    (void)in_sizes; (void)n_in; (void)out_size;
    const float* fft    = (const float*)d_in[0];
    const float* az     = (const float*)d_in[1];
    // d_in[2] = az_timestamps (unused)
    const float* map_pc = (const float*)d_in[3];
    const float* T_init = (const float*)d_in[4];
    const float* params = (const float*)d_in[5];
    float* out = (float*)d_out;

    extract_kernel<<<(B_*A_*32 + 127)/128, 128>>>(fft, az, params);

    cudaFuncSetAttribute(icp_kernel,
                         cudaFuncAttributeMaxDynamicSharedMemorySize,
                         (int)sizeof(IcpSmem));
    icp_kernel<<<B_, 1024, sizeof(IcpSmem)>>>(map_pc, T_init, out);
}

// round 3
// speedup vs baseline: 1.5908x; 1.5908x over previous
#include <cuda_runtime.h>
#include <math_constants.h>
#include <stdint.h>

// Problem constants
#define B_    8
#define A_    400
#define R_    1024
#define M_    4096
#define MC    6             // map_pc columns: x,y,z,nx,ny,nz
#define KPK   4
#define NPTS  (A_*KPK)      // 1600 scan points per batch
#define NIT   50
#define RESF  0.0596f
#define TRIMF 5.0f
#define GRID  64
#define CELLSZ 1.875f       // 120 / 64
#define INVCELL (1.0f/1.875f)
#define XMIN  (-60.0f)

#define CLU   4             // CTAs per batch (cluster size)
#define NTH   512           // threads per CTA
#define PPC   (NPTS/CLU)    // 400 points per CTA

// Scratch: extracted scan points + weights
__device__ float g_scanx[B_*NPTS];
__device__ float g_scany[B_*NPTS];
__device__ float g_scanw[B_*NPTS];

// ---------------------------------------------------------------------------
// cluster / DSMEM helpers
// ---------------------------------------------------------------------------
__device__ __forceinline__ uint32_t smem_u32(const void* p) {
    return (uint32_t)__cvta_generic_to_shared(p);
}
__device__ __forceinline__ uint32_t mapa_rank(uint32_t addr, uint32_t rank) {
    uint32_t r;
    asm("mapa.shared::cluster.u32 %0, %1, %2;" : "=r"(r) : "r"(addr), "r"(rank));
    return r;
}
__device__ __forceinline__ void st_cluster_f32(uint32_t addr, float v) {
    asm volatile("st.shared::cluster.f32 [%0], %1;" :: "r"(addr), "f"(v));
}
__device__ __forceinline__ uint32_t cluster_rank() {
    uint32_t r; asm("mov.u32 %0, %%cluster_ctarank;" : "=r"(r)); return r;
}
__device__ __forceinline__ void cluster_sync() {
    asm volatile("barrier.cluster.arrive.aligned;" ::: "memory");
    asm volatile("barrier.cluster.wait.aligned;" ::: "memory");
}

// ---------------------------------------------------------------------------
// Kernel 1: BFAR extraction. One warp per (b, a) row.
// ---------------------------------------------------------------------------
__global__ void extract_kernel(const float* __restrict__ fft,
                               const float* __restrict__ az,
                               const float* __restrict__ params) {
    int gtid = blockIdx.x * blockDim.x + threadIdx.x;
    int row  = gtid >> 5;
    int lane = gtid & 31;
    if (row >= B_ * A_) return;

    const float* rp = fft + (size_t)row * R_;

    float sum = 0.f;
    #pragma unroll
    for (int i = 0; i < R_/32; ++i) sum += rp[i*32 + lane];
    #pragma unroll
    for (int off = 16; off; off >>= 1) sum += __shfl_xor_sync(0xffffffffu, sum, off);
    float mean = sum * (1.0f / (float)R_);
    float pa = fmaxf(params[0], 0.f);
    float pb = fmaxf(params[1], 0.f);
    float thr = pa * mean + pb;

    float v0=-CUDART_INF_F, v1=-CUDART_INF_F, v2=-CUDART_INF_F, v3=-CUDART_INF_F;
    int   i0=0x7fffffff,   i1=0x7fffffff,   i2=0x7fffffff,   i3=0x7fffffff;
    #pragma unroll
    for (int i = 0; i < R_/32; ++i) {
        int idx = i*32 + lane;
        float sc = rp[idx] - thr;
        if (sc > v3) {
            v3 = sc; i3 = idx;
            if (v3 > v2) { float tv=v2; v2=v3; v3=tv; int ti=i2; i2=i3; i3=ti; }
            if (v2 > v1) { float tv=v1; v1=v2; v2=tv; int ti=i1; i1=i2; i2=ti; }
            if (v1 > v0) { float tv=v0; v0=v1; v1=tv; int ti=i0; i0=i1; i1=ti; }
        }
    }

    int ptr = 0;
    float outv = 0.f; int outi = 0;
    #pragma unroll
    for (int k = 0; k < KPK; ++k) {
        float cv = (ptr==0) ? v0 : (ptr==1) ? v1 : (ptr==2) ? v2 : (ptr==3) ? v3 : -CUDART_INF_F;
        int   ci = (ptr==0) ? i0 : (ptr==1) ? i1 : (ptr==2) ? i2 : (ptr==3) ? i3 : 0x7fffffff;
        float bv = cv; int bi = ci;
        #pragma unroll
        for (int off = 16; off; off >>= 1) {
            float ov = __shfl_xor_sync(0xffffffffu, bv, off);
            int   oi = __shfl_xor_sync(0xffffffffu, bi, off);
            if (ov > bv || (ov == bv && oi < bi)) { bv = ov; bi = oi; }
        }
        if (bi == ci && ptr < 4) ptr++;
        if (lane == k) { outv = bv; outi = bi; }
    }

    if (lane < KPK) {
        float rng = ((float)outi + 0.5f) * RESF;
        float azv = az[row];
        float x = rng * cosf(azv);
        float y = rng * sinf(azv);
        int o = row * KPK + lane;
        g_scanx[o] = x;
        g_scany[o] = y;
        g_scanw[o] = fmaxf(outv, 0.f);
    }
}

// ---------------------------------------------------------------------------
// Kernel 2: clustered ICP. 4 CTAs x 512 threads per batch; each CTA owns
// 400 scan points and a full smem copy of the map grid. Per-iteration
// cross-CTA reduction via DSMEM broadcast + single cluster.sync
// (double-buffered by parity).
// ---------------------------------------------------------------------------
struct IcpSmem {
    float4 smap[M_];               // binned (x, y, nx, ny)           64 KB
    int    cellStart[GRID*GRID+1]; // 16.4 KB
    int    cellOfs[GRID*GRID];     // 16.4 KB
    float  sx[PPC];
    float  sy[PPC];
    float  sw[PPC];                // 4.8 KB
    float  red[16][12];            // per-warp partials (padded)
    float  partial[2][CLU][12];    // [parity][rank][9] cross-CTA slots
    int    wsum[16];
    float  state[4];               // theta, tx, ty
};

__global__ void __launch_bounds__(NTH, 1) __cluster_dims__(CLU, 1, 1)
icp_kernel(const float* __restrict__ map_pc,
           const float* __restrict__ T_init,
           float* __restrict__ out) {
    extern __shared__ char smraw[];
    IcpSmem& S = *reinterpret_cast<IcpSmem*>(smraw);

    const int tid   = threadIdx.x;
    const int lane  = tid & 31;
    const int wid   = tid >> 5;
    const int crank = (int)cluster_rank();
    const int b     = blockIdx.x / CLU;
    const float* mp = map_pc + (size_t)b * M_ * MC;

    // --- build grid: count ---
    for (int c = tid; c < GRID*GRID; c += NTH) S.cellOfs[c] = 0;
    __syncthreads();
    for (int i = tid; i < M_; i += NTH) {
        float x = mp[i*MC + 0], y = mp[i*MC + 1];
        int gx = min(max((int)floorf((x - XMIN) * INVCELL), 0), GRID-1);
        int gy = min(max((int)floorf((y - XMIN) * INVCELL), 0), GRID-1);
        atomicAdd(&S.cellOfs[gy*GRID + gx], 1);
    }
    __syncthreads();

    // --- exclusive prefix scan over 4096 cells (8 cells / thread) ---
    {
        int base8 = tid * 8;
        int c[8], pre[8];
        int s = 0;
        #pragma unroll
        for (int j = 0; j < 8; ++j) { c[j] = S.cellOfs[base8 + j]; pre[j] = s; s += c[j]; }
        int v = s;
        #pragma unroll
        for (int off = 1; off < 32; off <<= 1) {
            int u = __shfl_up_sync(0xffffffffu, v, off);
            if (lane >= off) v += u;
        }
        if (lane == 31) S.wsum[wid] = v;
        __syncthreads();
        if (wid == 0 && lane < 16) {
            int wv = S.wsum[lane];
            #pragma unroll
            for (int off = 1; off < 16; off <<= 1) {
                int u = __shfl_up_sync(0x0000ffffu, wv, off);
                if (lane >= off) wv += u;
            }
            S.wsum[lane] = wv;
        }
        __syncthreads();
        int base = (v - s) + (wid ? S.wsum[wid-1] : 0);
        #pragma unroll
        for (int j = 0; j < 8; ++j) S.cellStart[base8 + j] = base + pre[j];
        if (tid == NTH-1) S.cellStart[GRID*GRID] = base + s;
    }
    __syncthreads();
    for (int c = tid; c < GRID*GRID; c += NTH) S.cellOfs[c] = S.cellStart[c];
    __syncthreads();

    // --- scatter map points (normalize 2D normals) ---
    for (int i = tid; i < M_; i += NTH) {
        float x  = mp[i*MC + 0], y  = mp[i*MC + 1];
        float nx = mp[i*MC + 3], ny = mp[i*MC + 4];
        float nrm = sqrtf(nx*nx + ny*ny);
        float d   = fmaxf(nrm, 1e-12f);
        nx /= d; ny /= d;
        int gx = min(max((int)floorf((x - XMIN) * INVCELL), 0), GRID-1);
        int gy = min(max((int)floorf((y - XMIN) * INVCELL), 0), GRID-1);
        int pos = atomicAdd(&S.cellOfs[gy*GRID + gx], 1);
        S.smap[pos] = make_float4(x, y, nx, ny);
    }

    // --- load this CTA's scan slice, init state ---
    if (tid < PPC) {
        int o = b*NPTS + crank*PPC + tid;
        S.sx[tid] = g_scanx[o];
        S.sy[tid] = g_scany[o];
        S.sw[tid] = g_scanw[o];
    }
    if (tid == 0) {
        const float* T = T_init + b*16;
        S.state[0] = atan2f(T[4], T[0]);
        S.state[1] = T[3];
        S.state[2] = T[7];
    }
    __syncthreads();
    cluster_sync();  // peers' smem ready before any DSMEM traffic

    const uint32_t partialBase = smem_u32(&S.partial[0][0][0]);

    // --- 50 GN iterations ---
    for (int it = 0; it < NIT; ++it) {
        const int parity = it & 1;
        float theta = S.state[0], tx = S.state[1], ty = S.state[2];
        float cth = cosf(theta), sth = sinf(theta);

        float a00=0.f,a01=0.f,a02=0.f,a11=0.f,a12=0.f,a22=0.f;
        float g0=0.f,g1=0.f,g2=0.f;

        if (tid < PPC) {
            float sxv = S.sx[tid], syv = S.sy[tid], wv = S.sw[tid];
            float px = cth*sxv - sth*syv + tx;
            float py = sth*sxv + cth*syv + ty;

            int cgx = min(max((int)floorf((px - XMIN) * INVCELL), 0), GRID-1);
            int cgy = min(max((int)floorf((py - XMIN) * INVCELL), 0), GRID-1);

            float bestd2 = 1e30f;
            int   bestk  = -1;

            auto scanSpan = [&](int gy, int xa, int xb) {
                if ((unsigned)gy >= (unsigned)GRID) return;
                xa = max(xa, 0); xb = min(xb, GRID-1);
                if (xa > xb) return;
                int k0 = S.cellStart[gy*GRID + xa];
                int k1 = S.cellStart[gy*GRID + xb + 1];
                for (int k = k0; k < k1; ++k) {
                    float4 m = S.smap[k];
                    float dx = px - m.x, dy = py - m.y;
                    float d2 = dx*dx + dy*dy;
                    if (d2 < bestd2) { bestd2 = d2; bestk = k; }
                }
            };

            for (int r = 0; r < GRID; ++r) {
                if (r >= 1) {
                    float mf = (float)(r-1) * CELLSZ;
                    if (mf*mf >= bestd2) break;
                    if (mf >= TRIMF && bestd2 >= TRIMF*TRIMF) break;
                }
                int xa = cgx - r, xb = cgx + r;
                int ylo = cgy - r, yhi = cgy + r;
                scanSpan(ylo, xa, xb);
                if (r > 0) {
                    scanSpan(yhi, xa, xb);
                    for (int gy = ylo + 1; gy <= yhi - 1; ++gy) {
                        scanSpan(gy, xa, xa);
                        scanSpan(gy, xb, xb);
                    }
                }
            }

            if (bestk >= 0 && bestd2 < TRIMF*TRIMF) {
                float4 m = S.smap[bestk];
                float res = m.z*(px - m.x) + m.w*(py - m.y);
                float hub = fminf(1.f, 1.f / fmaxf(fabsf(res), 1e-12f));
                float wt  = wv * hub;
                float dr0 = -sth*sxv - cth*syv;
                float dr1 =  cth*sxv - sth*syv;
                float j2  = m.z*dr0 + m.w*dr1;
                a00 = wt*m.z*m.z; a01 = wt*m.z*m.w; a02 = wt*m.z*j2;
                a11 = wt*m.w*m.w; a12 = wt*m.w*j2;  a22 = wt*j2*j2;
                g0  = wt*m.z*res; g1  = wt*m.w*res; g2  = wt*j2*res;
            }
        }

        // warp tree-reduce 9 values
        #pragma unroll
        for (int off = 16; off; off >>= 1) {
            a00 += __shfl_xor_sync(0xffffffffu, a00, off);
            a01 += __shfl_xor_sync(0xffffffffu, a01, off);
            a02 += __shfl_xor_sync(0xffffffffu, a02, off);
            a11 += __shfl_xor_sync(0xffffffffu, a11, off);
            a12 += __shfl_xor_sync(0xffffffffu, a12, off);
            a22 += __shfl_xor_sync(0xffffffffu, a22, off);
            g0  += __shfl_xor_sync(0xffffffffu, g0 , off);
            g1  += __shfl_xor_sync(0xffffffffu, g1 , off);
            g2  += __shfl_xor_sync(0xffffffffu, g2 , off);
        }
        if (lane == 0) {
            S.red[wid][0]=a00; S.red[wid][1]=a01; S.red[wid][2]=a02;
            S.red[wid][3]=a11; S.red[wid][4]=a12; S.red[wid][5]=a22;
            S.red[wid][6]=g0;  S.red[wid][7]=g1;  S.red[wid][8]=g2;
        }
        __syncthreads();

        // warp 0: reduce 16 warp partials, broadcast to all cluster CTAs
        if (wid == 0) {
            float r9[9];
            #pragma unroll
            for (int k = 0; k < 9; ++k) r9[k] = (lane < 16) ? S.red[lane][k] : 0.f;
            #pragma unroll
            for (int off = 8; off; off >>= 1) {
                #pragma unroll
                for (int k = 0; k < 9; ++k)
                    r9[k] += __shfl_xor_sync(0xffffffffu, r9[k], off);
            }
            if (lane == 0) {
                uint32_t slot = partialBase + (uint32_t)((parity*CLU + crank) * 12 * 4);
                #pragma unroll
                for (int t = 0; t < CLU; ++t) {
                    uint32_t dst = mapa_rank(slot, (uint32_t)t);
                    #pragma unroll
                    for (int k = 0; k < 9; ++k)
                        st_cluster_f32(dst + 4u*k, r9[k]);
                }
            }
        }

        cluster_sync();  // partials visible everywhere

        // every CTA redundantly sums + solves (identical fp32 -> identical state)
        if (tid == 0) {
            float r9[9];
            #pragma unroll
            for (int k = 0; k < 9; ++k)
                r9[k] = S.partial[parity][0][k] + S.partial[parity][1][k]
                      + S.partial[parity][2][k] + S.partial[parity][3][k];
            float A00 = r9[0] + 1e-8f, A01 = r9[1], A02 = r9[2];
            float A11 = r9[3] + 1e-8f, A12 = r9[4], A22 = r9[5] + 1e-8f;
            float G0 = r9[6], G1 = r9[7], G2 = r9[8];
            float l00 = sqrtf(fmaxf(A00, 1e-30f));
            float l10 = A01 / l00, l20 = A02 / l00;
            float l11 = sqrtf(fmaxf(A11 - l10*l10, 1e-30f));
            float l21 = (A12 - l20*l10) / l11;
            float l22 = sqrtf(fmaxf(A22 - l20*l20 - l21*l21, 1e-30f));
            float y0 = (-G0) / l00;
            float y1 = (-G1 - l10*y0) / l11;
            float y2 = (-G2 - l20*y0 - l21*y1) / l22;
            float x2 = y2 / l22;
            float x1 = (y1 - l21*x2) / l11;
            float x0 = (y0 - l10*x1 - l20*x2) / l00;
            S.state[0] = theta + x2;
            S.state[1] = tx + x0;
            S.state[2] = ty + x1;
        }
        __syncthreads();
    }

    if (tid == 0 && crank == 0) {
        float theta = S.state[0], tx = S.state[1], ty = S.state[2];
        float c = cosf(theta), s = sinf(theta);
        float* T = out + b*16;
        T[0]=c;   T[1]=-s;  T[2]=0.f; T[3]=tx;
        T[4]=s;   T[5]=c;   T[6]=0.f; T[7]=ty;
        T[8]=0.f; T[9]=0.f; T[10]=1.f;T[11]=0.f;
        T[12]=0.f;T[13]=0.f;T[14]=0.f;T[15]=1.f;
    }
    cluster_sync();  // no CTA exits while peers may still write partials
}

// ---------------------------------------------------------------------------
extern "C" void kernel_launch(void* const* d_in, const int* in_sizes, int n_in,
                              void* d_out, int out_size) {
    (void)in_sizes; (void)n_in; (void)out_size;
    const float* fft    = (const float*)d_in[0];
    const float* az     = (const float*)d_in[1];
    // d_in[2] = az_timestamps (unused)
    const float* map_pc = (const float*)d_in[3];
    const float* T_init = (const float*)d_in[4];
    const float* params = (const float*)d_in[5];
    float* out = (float*)d_out;

    extract_kernel<<<(B_*A_*32 + 127)/128, 128>>>(fft, az, params);

    cudaFuncSetAttribute(icp_kernel,
                         cudaFuncAttributeMaxDynamicSharedMemorySize,
                         (int)sizeof(IcpSmem));
    icp_kernel<<<B_*CLU, NTH, sizeof(IcpSmem)>>>(map_pc, T_init, out);
}

// round 4
// speedup vs baseline: 1.7355x; 1.0910x over previous
#include <cuda_runtime.h>
#include <math_constants.h>
#include <stdint.h>

// Problem constants
#define B_    8
#define A_    400
#define R_    1024
#define M_    4096
#define MC    6             // map_pc columns: x,y,z,nx,ny,nz
#define KPK   4
#define NPTS  (A_*KPK)      // 1600 scan points per batch
#define NIT   50
#define RESF  0.0596f
#define TRIMF 5.0f
#define GRID  64
#define CELLSZ 1.875f       // 120 / 64
#define INVCELL (1.0f/1.875f)
#define XMIN  (-60.0f)

#define CLU   4             // CTAs per batch (cluster size)
#define NTH   512           // threads per CTA
#define PPC   (NPTS/CLU)    // 400 points per CTA

// Scratch: extracted scan points + weights
__device__ float g_scanx[B_*NPTS];
__device__ float g_scany[B_*NPTS];
__device__ float g_scanw[B_*NPTS];

// ---------------------------------------------------------------------------
// cluster / DSMEM helpers
// ---------------------------------------------------------------------------
__device__ __forceinline__ uint32_t smem_u32(const void* p) {
    return (uint32_t)__cvta_generic_to_shared(p);
}
__device__ __forceinline__ uint32_t mapa_rank(uint32_t addr, uint32_t rank) {
    uint32_t r;
    asm("mapa.shared::cluster.u32 %0, %1, %2;" : "=r"(r) : "r"(addr), "r"(rank));
    return r;
}
__device__ __forceinline__ void st_cluster_f32(uint32_t addr, float v) {
    asm volatile("st.shared::cluster.f32 [%0], %1;" :: "r"(addr), "f"(v));
}
__device__ __forceinline__ uint32_t cluster_rank() {
    uint32_t r; asm("mov.u32 %0, %%cluster_ctarank;" : "=r"(r)); return r;
}
__device__ __forceinline__ void cluster_sync() {
    asm volatile("barrier.cluster.arrive.aligned;" ::: "memory");
    asm volatile("barrier.cluster.wait.aligned;" ::: "memory");
}

// ---------------------------------------------------------------------------
// Kernel 1: BFAR extraction. One warp per (b, a) row.
// ---------------------------------------------------------------------------
__global__ void extract_kernel(const float* __restrict__ fft,
                               const float* __restrict__ az,
                               const float* __restrict__ params) {
    int gtid = blockIdx.x * blockDim.x + threadIdx.x;
    int row  = gtid >> 5;
    int lane = gtid & 31;
    if (row >= B_ * A_) return;

    const float* rp = fft + (size_t)row * R_;

    float sum = 0.f;
    #pragma unroll
    for (int i = 0; i < R_/32; ++i) sum += rp[i*32 + lane];
    #pragma unroll
    for (int off = 16; off; off >>= 1) sum += __shfl_xor_sync(0xffffffffu, sum, off);
    float mean = sum * (1.0f / (float)R_);
    float pa = fmaxf(params[0], 0.f);
    float pb = fmaxf(params[1], 0.f);
    float thr = pa * mean + pb;

    float v0=-CUDART_INF_F, v1=-CUDART_INF_F, v2=-CUDART_INF_F, v3=-CUDART_INF_F;
    int   i0=0x7fffffff,   i1=0x7fffffff,   i2=0x7fffffff,   i3=0x7fffffff;
    #pragma unroll
    for (int i = 0; i < R_/32; ++i) {
        int idx = i*32 + lane;
        float sc = rp[idx] - thr;
        if (sc > v3) {
            v3 = sc; i3 = idx;
            if (v3 > v2) { float tv=v2; v2=v3; v3=tv; int ti=i2; i2=i3; i3=ti; }
            if (v2 > v1) { float tv=v1; v1=v2; v2=tv; int ti=i1; i1=i2; i2=ti; }
            if (v1 > v0) { float tv=v0; v0=v1; v1=tv; int ti=i0; i0=i1; i1=ti; }
        }
    }

    int ptr = 0;
    float outv = 0.f; int outi = 0;
    #pragma unroll
    for (int k = 0; k < KPK; ++k) {
        float cv = (ptr==0) ? v0 : (ptr==1) ? v1 : (ptr==2) ? v2 : (ptr==3) ? v3 : -CUDART_INF_F;
        int   ci = (ptr==0) ? i0 : (ptr==1) ? i1 : (ptr==2) ? i2 : (ptr==3) ? i3 : 0x7fffffff;
        float bv = cv; int bi = ci;
        #pragma unroll
        for (int off = 16; off; off >>= 1) {
            float ov = __shfl_xor_sync(0xffffffffu, bv, off);
            int   oi = __shfl_xor_sync(0xffffffffu, bi, off);
            if (ov > bv || (ov == bv && oi < bi)) { bv = ov; bi = oi; }
        }
        if (bi == ci && ptr < 4) ptr++;
        if (lane == k) { outv = bv; outi = bi; }
    }

    if (lane < KPK) {
        float rng = ((float)outi + 0.5f) * RESF;
        float azv = az[row];
        float x = rng * cosf(azv);
        float y = rng * sinf(azv);
        int o = row * KPK + lane;
        g_scanx[o] = x;
        g_scany[o] = y;
        g_scanw[o] = fmaxf(outv, 0.f);
    }
}

// ---------------------------------------------------------------------------
// Kernel 2: clustered ICP. 4 CTAs x 512 threads per batch; 1 point/thread.
// Branch-uniform 3x3 NN phase + rare exact-margin ring extension.
// Register-resident pose state; 1 __syncthreads + 1 cluster.sync per iter.
// ---------------------------------------------------------------------------
struct IcpSmem {
    float4 smap[M_];               // binned (x, y, nx, ny)           64 KB
    int    cellStart[GRID*GRID+1]; // 16.4 KB
    int    cellOfs[GRID*GRID];     // 16.4 KB
    float  red[16][12];            // per-warp partials (padded)
    float  partial[2][CLU][12];    // [parity][rank][9] cross-CTA slots
    int    wsum[16];
};

__global__ void __launch_bounds__(NTH, 1) __cluster_dims__(CLU, 1, 1)
icp_kernel(const float* __restrict__ map_pc,
           const float* __restrict__ T_init,
           float* __restrict__ out) {
    extern __shared__ char smraw[];
    IcpSmem& S = *reinterpret_cast<IcpSmem*>(smraw);

    const int tid   = threadIdx.x;
    const int lane  = tid & 31;
    const int wid   = tid >> 5;
    const int crank = (int)cluster_rank();
    const int b     = blockIdx.x / CLU;
    const float* mp = map_pc + (size_t)b * M_ * MC;

    // --- build grid: count ---
    for (int c = tid; c < GRID*GRID; c += NTH) S.cellOfs[c] = 0;
    __syncthreads();
    for (int i = tid; i < M_; i += NTH) {
        float x = mp[i*MC + 0], y = mp[i*MC + 1];
        int gx = min(max((int)floorf((x - XMIN) * INVCELL), 0), GRID-1);
        int gy = min(max((int)floorf((y - XMIN) * INVCELL), 0), GRID-1);
        atomicAdd(&S.cellOfs[gy*GRID + gx], 1);
    }
    __syncthreads();

    // --- exclusive prefix scan over 4096 cells (8 cells / thread) ---
    {
        int base8 = tid * 8;
        int c[8], pre[8];
        int s = 0;
        #pragma unroll
        for (int j = 0; j < 8; ++j) { c[j] = S.cellOfs[base8 + j]; pre[j] = s; s += c[j]; }
        int v = s;
        #pragma unroll
        for (int off = 1; off < 32; off <<= 1) {
            int u = __shfl_up_sync(0xffffffffu, v, off);
            if (lane >= off) v += u;
        }
        if (lane == 31) S.wsum[wid] = v;
        __syncthreads();
        if (wid == 0 && lane < 16) {
            int wv = S.wsum[lane];
            #pragma unroll
            for (int off = 1; off < 16; off <<= 1) {
                int u = __shfl_up_sync(0x0000ffffu, wv, off);
                if (lane >= off) wv += u;
            }
            S.wsum[lane] = wv;
        }
        __syncthreads();
        int base = (v - s) + (wid ? S.wsum[wid-1] : 0);
        #pragma unroll
        for (int j = 0; j < 8; ++j) S.cellStart[base8 + j] = base + pre[j];
        if (tid == NTH-1) S.cellStart[GRID*GRID] = base + s;
    }
    __syncthreads();
    for (int c = tid; c < GRID*GRID; c += NTH) S.cellOfs[c] = S.cellStart[c];
    __syncthreads();

    // --- scatter map points (normalize 2D normals) ---
    for (int i = tid; i < M_; i += NTH) {
        float x  = mp[i*MC + 0], y  = mp[i*MC + 1];
        float nx = mp[i*MC + 3], ny = mp[i*MC + 4];
        float nrm = sqrtf(nx*nx + ny*ny);
        float d   = fmaxf(nrm, 1e-12f);
        nx /= d; ny /= d;
        int gx = min(max((int)floorf((x - XMIN) * INVCELL), 0), GRID-1);
        int gy = min(max((int)floorf((y - XMIN) * INVCELL), 0), GRID-1);
        int pos = atomicAdd(&S.cellOfs[gy*GRID + gx], 1);
        S.smap[pos] = make_float4(x, y, nx, ny);
    }

    // --- this thread's scan point (register resident) ---
    float sxv = 0.f, syv = 0.f, wv = 0.f;
    if (tid < PPC) {
        int o = b*NPTS + crank*PPC + tid;
        sxv = g_scanx[o];
        syv = g_scany[o];
        wv  = g_scanw[o];
    }
    // pose state, identical in every thread
    float theta, tx, ty;
    {
        const float* T = T_init + b*16;
        theta = atan2f(T[4], T[0]);
        tx = T[3];
        ty = T[7];
    }
    __syncthreads();
    cluster_sync();  // peers' smem ready before DSMEM traffic

    const uint32_t partialBase = smem_u32(&S.partial[0][0][0]);
    const float trim2 = TRIMF * TRIMF;

    // --- 50 GN iterations ---
    for (int it = 0; it < NIT; ++it) {
        const int parity = it & 1;
        float cth = cosf(theta), sth = sinf(theta);

        float a00=0.f,a01=0.f,a02=0.f,a11=0.f,a12=0.f,a22=0.f;
        float g0=0.f,g1=0.f,g2=0.f;

        if (tid < PPC) {
            float px = cth*sxv - sth*syv + tx;
            float py = sth*sxv + cth*syv + ty;

            int cgx = min(max((int)floorf((px - XMIN) * INVCELL), 0), GRID-1);
            int cgy = min(max((int)floorf((py - XMIN) * INVCELL), 0), GRID-1);

            float bestd2 = 1e30f;
            int   bestk  = -1;

            // ---- phase 1: uniform 3x3 scan ----
            {
                int xa = max(cgx-1, 0), xb = min(cgx+1, GRID-1);
                int ya = max(cgy-1, 0), yb = min(cgy+1, GRID-1);
                for (int gy = ya; gy <= yb; ++gy) {
                    int rowb = gy*GRID;
                    int k0 = S.cellStart[rowb + xa];
                    int k1 = S.cellStart[rowb + xb + 1];
                    for (int k = k0; k < k1; ++k) {
                        float4 m = S.smap[k];
                        float dx = px - m.x, dy = py - m.y;
                        float d2 = dx*dx + dy*dy;
                        if (d2 < bestd2) { bestd2 = d2; bestk = k; }
                    }
                }
            }

            // ---- phase 2: rare ring extension with exact margins ----
            {
                auto scanSpan = [&](int gy, int xa, int xb) {
                    if ((unsigned)gy >= (unsigned)GRID) return;
                    xa = max(xa, 0); xb = min(xb, GRID-1);
                    if (xa > xb) return;
                    int k0 = S.cellStart[gy*GRID + xa];
                    int k1 = S.cellStart[gy*GRID + xb + 1];
                    for (int k = k0; k < k1; ++k) {
                        float4 m = S.smap[k];
                        float dx = px - m.x, dy = py - m.y;
                        float d2 = dx*dx + dy*dy;
                        if (d2 < bestd2) { bestd2 = d2; bestk = k; }
                    }
                };
                for (int r = 2; r < GRID; ++r) {
                    int s = r - 1;   // half-width of already-scanned square
                    // exact distance from p to nearest unscanned cell region
                    float dL = (cgx - s <= 0)        ? 1e30f : px - (XMIN + (float)(cgx - s) * CELLSZ);
                    float dR = (cgx + s >= GRID-1)   ? 1e30f : (XMIN + (float)(cgx + s + 1) * CELLSZ) - px;
                    float dB = (cgy - s <= 0)        ? 1e30f : py - (XMIN + (float)(cgy - s) * CELLSZ);
                    float dT = (cgy + s >= GRID-1)   ? 1e30f : (XMIN + (float)(cgy + s + 1) * CELLSZ) - py;
                    float mf = fminf(fminf(dL, dR), fminf(dB, dT));
                    float lim = fminf(bestd2, trim2);
                    if (mf*mf >= lim) break;
                    int xa = cgx - r, xb = cgx + r;
                    int ylo = cgy - r, yhi = cgy + r;
                    scanSpan(ylo, xa, xb);
                    scanSpan(yhi, xa, xb);
                    for (int gy = ylo + 1; gy <= yhi - 1; ++gy) {
                        scanSpan(gy, xa, xa);
                        scanSpan(gy, xb, xb);
                    }
                }
            }

            if (bestk >= 0 && bestd2 < trim2) {
                float4 m = S.smap[bestk];
                float res = m.z*(px - m.x) + m.w*(py - m.y);
                float hub = fminf(1.f, 1.f / fmaxf(fabsf(res), 1e-12f));
                float wt  = wv * hub;
                float dr0 = -sth*sxv - cth*syv;
                float dr1 =  cth*sxv - sth*syv;
                float j2  = m.z*dr0 + m.w*dr1;
                a00 = wt*m.z*m.z; a01 = wt*m.z*m.w; a02 = wt*m.z*j2;
                a11 = wt*m.w*m.w; a12 = wt*m.w*j2;  a22 = wt*j2*j2;
                g0  = wt*m.z*res; g1  = wt*m.w*res; g2  = wt*j2*res;
            }
        }

        // warp tree-reduce 9 values
        #pragma unroll
        for (int off = 16; off; off >>= 1) {
            a00 += __shfl_xor_sync(0xffffffffu, a00, off);
            a01 += __shfl_xor_sync(0xffffffffu, a01, off);
            a02 += __shfl_xor_sync(0xffffffffu, a02, off);
            a11 += __shfl_xor_sync(0xffffffffu, a11, off);
            a12 += __shfl_xor_sync(0xffffffffu, a12, off);
            a22 += __shfl_xor_sync(0xffffffffu, a22, off);
            g0  += __shfl_xor_sync(0xffffffffu, g0 , off);
            g1  += __shfl_xor_sync(0xffffffffu, g1 , off);
            g2  += __shfl_xor_sync(0xffffffffu, g2 , off);
        }
        if (lane == 0) {
            S.red[wid][0]=a00; S.red[wid][1]=a01; S.red[wid][2]=a02;
            S.red[wid][3]=a11; S.red[wid][4]=a12; S.red[wid][5]=a22;
            S.red[wid][6]=g0;  S.red[wid][7]=g1;  S.red[wid][8]=g2;
        }
        __syncthreads();

        // warp 0: reduce 16 warp partials, broadcast to all cluster CTAs
        if (wid == 0) {
            float r9[9];
            #pragma unroll
            for (int k = 0; k < 9; ++k) r9[k] = (lane < 16) ? S.red[lane][k] : 0.f;
            #pragma unroll
            for (int off = 8; off; off >>= 1) {
                #pragma unroll
                for (int k = 0; k < 9; ++k)
                    r9[k] += __shfl_xor_sync(0xffffffffu, r9[k], off);
            }
            if (lane == 0) {
                uint32_t slot = partialBase + (uint32_t)((parity*CLU + crank) * 12 * 4);
                #pragma unroll
                for (int t = 0; t < CLU; ++t) {
                    uint32_t dst = mapa_rank(slot, (uint32_t)t);
                    #pragma unroll
                    for (int k = 0; k < 9; ++k)
                        st_cluster_f32(dst + 4u*k, r9[k]);
                }
            }
        }

        cluster_sync();  // partials visible everywhere

        // every THREAD redundantly sums + solves (identical fp32 everywhere)
        {
            float r9[9];
            #pragma unroll
            for (int k = 0; k < 9; ++k)
                r9[k] = S.partial[parity][0][k] + S.partial[parity][1][k]
                      + S.partial[parity][2][k] + S.partial[parity][3][k];
            float A00 = r9[0] + 1e-8f, A01 = r9[1], A02 = r9[2];
            float A11 = r9[3] + 1e-8f, A12 = r9[4], A22 = r9[5] + 1e-8f;
            float G0 = r9[6], G1 = r9[7], G2 = r9[8];
            float l00 = sqrtf(fmaxf(A00, 1e-30f));
            float l10 = A01 / l00, l20 = A02 / l00;
            float l11 = sqrtf(fmaxf(A11 - l10*l10, 1e-30f));
            float l21 = (A12 - l20*l10) / l11;
            float l22 = sqrtf(fmaxf(A22 - l20*l20 - l21*l21, 1e-30f));
            float y0 = (-G0) / l00;
            float y1 = (-G1 - l10*y0) / l11;
            float y2 = (-G2 - l20*y0 - l21*y1) / l22;
            float x2 = y2 / l22;
            float x1 = (y1 - l21*x2) / l11;
            float x0 = (y0 - l10*x1 - l20*x2) / l00;
            theta += x2;
            tx += x0;
            ty += x1;
        }
        // no trailing barrier: state is register-resident and identical
    }

    if (tid == 0 && crank == 0) {
        float c = cosf(theta), s = sinf(theta);
        float* T = out + b*16;
        T[0]=c;   T[1]=-s;  T[2]=0.f; T[3]=tx;
        T[4]=s;   T[5]=c;   T[6]=0.f; T[7]=ty;
        T[8]=0.f; T[9]=0.f; T[10]=1.f;T[11]=0.f;
        T[12]=0.f;T[13]=0.f;T[14]=0.f;T[15]=1.f;
    }
    // last DSMEM writes precede the final in-loop cluster.sync -> safe to exit
}

// ---------------------------------------------------------------------------
extern "C" void kernel_launch(void* const* d_in, const int* in_sizes, int n_in,
                              void* d_out, int out_size) {
    (void)in_sizes; (void)n_in; (void)out_size;
    const float* fft    = (const float*)d_in[0];
    const float* az     = (const float*)d_in[1];
    // d_in[2] = az_timestamps (unused)
    const float* map_pc = (const float*)d_in[3];
    const float* T_init = (const float*)d_in[4];
    const float* params = (const float*)d_in[5];
    float* out = (float*)d_out;

    extract_kernel<<<(B_*A_*32 + 127)/128, 128>>>(fft, az, params);

    cudaFuncSetAttribute(icp_kernel,
                         cudaFuncAttributeMaxDynamicSharedMemorySize,
                         (int)sizeof(IcpSmem));
    icp_kernel<<<B_*CLU, NTH, sizeof(IcpSmem)>>>(map_pc, T_init, out);
}

// round 5
// speedup vs baseline: 1.8948x; 1.0917x over previous
#include <cuda_runtime.h>
#include <math_constants.h>
#include <stdint.h>

// Problem constants
#define B_    8
#define A_    400
#define R_    1024
#define M_    4096
#define MC    6             // map_pc columns: x,y,z,nx,ny,nz
#define KPK   4
#define NPTS  (A_*KPK)      // 1600 scan points per batch
#define NIT   50
#define RESF  0.0596f
#define TRIMF 5.0f
#define GRID  64
#define CELLSZ 1.875f       // 120 / 64
#define INVCELL (1.0f/1.875f)
#define XMIN  (-60.0f)

#define CLU   4             // CTAs per batch (cluster size)
#define NTH   512           // threads per CTA
#define PPC   (NPTS/CLU)    // 400 points per CTA

// Scratch: extracted scan points + weights
__device__ float g_scanx[B_*NPTS];
__device__ float g_scany[B_*NPTS];
__device__ float g_scanw[B_*NPTS];

// ---------------------------------------------------------------------------
// cluster / DSMEM helpers
// ---------------------------------------------------------------------------
__device__ __forceinline__ uint32_t smem_u32(const void* p) {
    return (uint32_t)__cvta_generic_to_shared(p);
}
__device__ __forceinline__ uint32_t mapa_rank(uint32_t addr, uint32_t rank) {
    uint32_t r;
    asm("mapa.shared::cluster.u32 %0, %1, %2;" : "=r"(r) : "r"(addr), "r"(rank));
    return r;
}
__device__ __forceinline__ void st_cluster_f32(uint32_t addr, float v) {
    asm volatile("st.shared::cluster.f32 [%0], %1;" :: "r"(addr), "f"(v));
}
__device__ __forceinline__ uint32_t cluster_rank() {
    uint32_t r; asm("mov.u32 %0, %%cluster_ctarank;" : "=r"(r)); return r;
}
__device__ __forceinline__ void cluster_sync() {
    asm volatile("barrier.cluster.arrive.aligned;" ::: "memory");
    asm volatile("barrier.cluster.wait.aligned;" ::: "memory");
}
__device__ __forceinline__ int morton6(int x, int y) {
    int m = 0;
    #pragma unroll
    for (int b = 0; b < 6; ++b)
        m |= (((x >> b) & 1) << (2*b)) | (((y >> b) & 1) << (2*b + 1));
    return m;
}

// ---------------------------------------------------------------------------
// Kernel 1: BFAR extraction. One warp per (b, a) row.
// ---------------------------------------------------------------------------
__global__ void extract_kernel(const float* __restrict__ fft,
                               const float* __restrict__ az,
                               const float* __restrict__ params) {
    int gtid = blockIdx.x * blockDim.x + threadIdx.x;
    int row  = gtid >> 5;
    int lane = gtid & 31;
    if (row >= B_ * A_) return;

    const float* rp = fft + (size_t)row * R_;

    float sum = 0.f;
    #pragma unroll
    for (int i = 0; i < R_/32; ++i) sum += rp[i*32 + lane];
    #pragma unroll
    for (int off = 16; off; off >>= 1) sum += __shfl_xor_sync(0xffffffffu, sum, off);
    float mean = sum * (1.0f / (float)R_);
    float pa = fmaxf(params[0], 0.f);
    float pb = fmaxf(params[1], 0.f);
    float thr = pa * mean + pb;

    float v0=-CUDART_INF_F, v1=-CUDART_INF_F, v2=-CUDART_INF_F, v3=-CUDART_INF_F;
    int   i0=0x7fffffff,   i1=0x7fffffff,   i2=0x7fffffff,   i3=0x7fffffff;
    #pragma unroll
    for (int i = 0; i < R_/32; ++i) {
        int idx = i*32 + lane;
        float sc = rp[idx] - thr;
        if (sc > v3) {
            v3 = sc; i3 = idx;
            if (v3 > v2) { float tv=v2; v2=v3; v3=tv; int ti=i2; i2=i3; i3=ti; }
            if (v2 > v1) { float tv=v1; v1=v2; v2=tv; int ti=i1; i1=i2; i2=ti; }
            if (v1 > v0) { float tv=v0; v0=v1; v1=tv; int ti=i0; i0=i1; i1=ti; }
        }
    }

    int ptr = 0;
    float outv = 0.f; int outi = 0;
    #pragma unroll
    for (int k = 0; k < KPK; ++k) {
        float cv = (ptr==0) ? v0 : (ptr==1) ? v1 : (ptr==2) ? v2 : (ptr==3) ? v3 : -CUDART_INF_F;
        int   ci = (ptr==0) ? i0 : (ptr==1) ? i1 : (ptr==2) ? i2 : (ptr==3) ? i3 : 0x7fffffff;
        float bv = cv; int bi = ci;
        #pragma unroll
        for (int off = 16; off; off >>= 1) {
            float ov = __shfl_xor_sync(0xffffffffu, bv, off);
            int   oi = __shfl_xor_sync(0xffffffffu, bi, off);
            if (ov > bv || (ov == bv && oi < bi)) { bv = ov; bi = oi; }
        }
        if (bi == ci && ptr < 4) ptr++;
        if (lane == k) { outv = bv; outi = bi; }
    }

    if (lane < KPK) {
        float rng = ((float)outi + 0.5f) * RESF;
        float azv = az[row];
        float x = rng * cosf(azv);
        float y = rng * sinf(azv);
        int o = row * KPK + lane;
        g_scanx[o] = x;
        g_scany[o] = y;
        g_scanw[o] = fmaxf(outv, 0.f);
    }
}

// ---------------------------------------------------------------------------
// Kernel 2: clustered ICP. 4 CTAs x 512 threads per batch; 1 point/thread,
// points Morton-sorted per CTA so warp lanes are spatially coherent.
// ---------------------------------------------------------------------------
struct IcpSmem {
    float4 smap[M_];               // binned (x, y, nx, ny)           64 KB
    int    cellStart[GRID*GRID+1]; // 16.4 KB
    int    cellOfs[GRID*GRID];     // map cursors, then sort hist     16.4 KB
    float  srtx[PPC];
    float  srty[PPC];
    float  srtw[PPC];              // sorted scan staging             4.8 KB
    float  red[16][12];            // per-warp partials (padded)
    float4 partial[2][CLU][3];     // [parity][rank][9 of 12] cross-CTA
    int    wsum[16];
};

// exclusive prefix scan over 4096 ints in smem arr, 512 threads.
// Returns: arr[c] <- exclusive prefix sum. Uses wsum[16].
__device__ __forceinline__ void scan4096(int* arr, int* wsum,
                                         int tid, int lane, int wid, int totStore,
                                         int* cellStartTotal) {
    int base8 = tid * 8;
    int c[8], pre[8];
    int s = 0;
    #pragma unroll
    for (int j = 0; j < 8; ++j) { c[j] = arr[base8 + j]; pre[j] = s; s += c[j]; }
    int v = s;
    #pragma unroll
    for (int off = 1; off < 32; off <<= 1) {
        int u = __shfl_up_sync(0xffffffffu, v, off);
        if (lane >= off) v += u;
    }
    if (lane == 31) wsum[wid] = v;
    __syncthreads();
    if (wid == 0 && lane < 16) {
        int wv = wsum[lane];
        #pragma unroll
        for (int off = 1; off < 16; off <<= 1) {
            int u = __shfl_up_sync(0x0000ffffu, wv, off);
            if (lane >= off) wv += u;
        }
        wsum[lane] = wv;
    }
    __syncthreads();
    int base = (v - s) + (wid ? wsum[wid-1] : 0);
    #pragma unroll
    for (int j = 0; j < 8; ++j) arr[base8 + j] = base + pre[j];
    if (totStore && tid == NTH-1) *cellStartTotal = base + s;
    __syncthreads();
}

__global__ void __launch_bounds__(NTH, 1) __cluster_dims__(CLU, 1, 1)
icp_kernel(const float* __restrict__ map_pc,
           const float* __restrict__ T_init,
           float* __restrict__ out) {
    extern __shared__ char smraw[];
    IcpSmem& S = *reinterpret_cast<IcpSmem*>(smraw);

    const int tid   = threadIdx.x;
    const int lane  = tid & 31;
    const int wid   = tid >> 5;
    const int crank = (int)cluster_rank();
    const int b     = blockIdx.x / CLU;
    const float* mp = map_pc + (size_t)b * M_ * MC;

    // --- build map grid: count ---
    for (int c = tid; c < GRID*GRID; c += NTH) S.cellOfs[c] = 0;
    __syncthreads();
    for (int i = tid; i < M_; i += NTH) {
        float x = mp[i*MC + 0], y = mp[i*MC + 1];
        int gx = min(max((int)floorf((x - XMIN) * INVCELL), 0), GRID-1);
        int gy = min(max((int)floorf((y - XMIN) * INVCELL), 0), GRID-1);
        atomicAdd(&S.cellOfs[gy*GRID + gx], 1);
    }
    __syncthreads();

    // exclusive scan -> cellOfs holds starts; copy into cellStart
    scan4096(S.cellOfs, S.wsum, tid, lane, wid, 1, &S.cellStart[GRID*GRID]);
    for (int c = tid; c < GRID*GRID; c += NTH) S.cellStart[c] = S.cellOfs[c];
    __syncthreads();

    // --- scatter map points (normalize 2D normals); cellOfs = cursors ---
    for (int i = tid; i < M_; i += NTH) {
        float x  = mp[i*MC + 0], y  = mp[i*MC + 1];
        float nx = mp[i*MC + 3], ny = mp[i*MC + 4];
        float nrm = sqrtf(nx*nx + ny*ny);
        float d   = fmaxf(nrm, 1e-12f);
        nx /= d; ny /= d;
        int gx = min(max((int)floorf((x - XMIN) * INVCELL), 0), GRID-1);
        int gy = min(max((int)floorf((y - XMIN) * INVCELL), 0), GRID-1);
        int pos = atomicAdd(&S.cellOfs[gy*GRID + gx], 1);
        S.smap[pos] = make_float4(x, y, nx, ny);
    }

    // pose state, identical in every thread
    float theta, tx, ty;
    {
        const float* T = T_init + b*16;
        theta = atan2f(T[4], T[0]);
        tx = T[3];
        ty = T[7];
    }

    // --- one-time Morton counting-sort of this CTA's 400 scan points ---
    float rawx = 0.f, rawy = 0.f, raww = 0.f;
    int mykey = 0;
    {
        float c0 = cosf(theta), s0 = sinf(theta);
        if (tid < PPC) {
            int o = b*NPTS + crank*PPC + tid;
            rawx = g_scanx[o];
            rawy = g_scany[o];
            raww = g_scanw[o];
            float px = c0*rawx - s0*rawy + tx;
            float py = s0*rawx + c0*rawy + ty;
            int gx = min(max((int)floorf((px - XMIN) * INVCELL), 0), GRID-1);
            int gy = min(max((int)floorf((py - XMIN) * INVCELL), 0), GRID-1);
            mykey = morton6(gx, gy);
        }
        __syncthreads();  // map scatter done; cellOfs reusable as histogram
        for (int c = tid; c < GRID*GRID; c += NTH) S.cellOfs[c] = 0;
        __syncthreads();
        if (tid < PPC) atomicAdd(&S.cellOfs[mykey], 1);
        __syncthreads();
        scan4096(S.cellOfs, S.wsum, tid, lane, wid, 0, nullptr);
        if (tid < PPC) {
            int pos = atomicAdd(&S.cellOfs[mykey], 1);
            S.srtx[pos] = rawx;
            S.srty[pos] = rawy;
            S.srtw[pos] = raww;
        }
        __syncthreads();
    }

    // this thread's (sorted) scan point, register resident
    float sxv = 0.f, syv = 0.f, wv = 0.f;
    if (tid < PPC) {
        sxv = S.srtx[tid];
        syv = S.srty[tid];
        wv  = S.srtw[tid];
    }
    __syncthreads();
    cluster_sync();  // peers' smem ready before DSMEM traffic

    const uint32_t partialBase = smem_u32(&S.partial[0][0][0]);
    const float trim2 = TRIMF * TRIMF;

    // --- 50 GN iterations ---
    for (int it = 0; it < NIT; ++it) {
        const int parity = it & 1;
        float cth = cosf(theta), sth = sinf(theta);

        float a00=0.f,a01=0.f,a02=0.f,a11=0.f,a12=0.f,a22=0.f;
        float g0=0.f,g1=0.f,g2=0.f;

        if (tid < PPC) {
            float px = cth*sxv - sth*syv + tx;
            float py = sth*sxv + cth*syv + ty;

            int cgx = min(max((int)floorf((px - XMIN) * INVCELL), 0), GRID-1);
            int cgy = min(max((int)floorf((py - XMIN) * INVCELL), 0), GRID-1);

            float bestd2 = 1e30f;
            int   bestk  = -1;

            // ---- phase 1: uniform 3x3 scan (lanes spatially coherent) ----
            {
                int xa = max(cgx-1, 0), xb = min(cgx+1, GRID-1);
                int ya = max(cgy-1, 0), yb = min(cgy+1, GRID-1);
                for (int gy = ya; gy <= yb; ++gy) {
                    int rowb = gy*GRID;
                    int k0 = S.cellStart[rowb + xa];
                    int k1 = S.cellStart[rowb + xb + 1];
                    for (int k = k0; k < k1; ++k) {
                        float4 m = S.smap[k];
                        float dx = px - m.x, dy = py - m.y;
                        float d2 = dx*dx + dy*dy;
                        if (d2 < bestd2) { bestd2 = d2; bestk = k; }
                    }
                }
            }

            // ---- phase 2: rare ring extension with exact margins ----
            {
                auto scanSpan = [&](int gy, int xa, int xb) {
                    if ((unsigned)gy >= (unsigned)GRID) return;
                    xa = max(xa, 0); xb = min(xb, GRID-1);
                    if (xa > xb) return;
                    int k0 = S.cellStart[gy*GRID + xa];
                    int k1 = S.cellStart[gy*GRID + xb + 1];
                    for (int k = k0; k < k1; ++k) {
                        float4 m = S.smap[k];
                        float dx = px - m.x, dy = py - m.y;
                        float d2 = dx*dx + dy*dy;
                        if (d2 < bestd2) { bestd2 = d2; bestk = k; }
                    }
                };
                for (int r = 2; r < GRID; ++r) {
                    int s = r - 1;   // half-width of already-scanned square
                    float dL = (cgx - s <= 0)        ? 1e30f : px - (XMIN + (float)(cgx - s) * CELLSZ);
                    float dR = (cgx + s >= GRID-1)   ? 1e30f : (XMIN + (float)(cgx + s + 1) * CELLSZ) - px;
                    float dB = (cgy - s <= 0)        ? 1e30f : py - (XMIN + (float)(cgy - s) * CELLSZ);
                    float dT = (cgy + s >= GRID-1)   ? 1e30f : (XMIN + (float)(cgy + s + 1) * CELLSZ) - py;
                    float mf = fminf(fminf(dL, dR), fminf(dB, dT));
                    float lim = fminf(bestd2, trim2);
                    if (mf*mf >= lim) break;
                    int xa = cgx - r, xb = cgx + r;
                    int ylo = cgy - r, yhi = cgy + r;
                    scanSpan(ylo, xa, xb);
                    scanSpan(yhi, xa, xb);
                    for (int gy = ylo + 1; gy <= yhi - 1; ++gy) {
                        scanSpan(gy, xa, xa);
                        scanSpan(gy, xb, xb);
                    }
                }
            }

            if (bestk >= 0 && bestd2 < trim2) {
                float4 m = S.smap[bestk];
                float res = m.z*(px - m.x) + m.w*(py - m.y);
                float hub = fminf(1.f, 1.f / fmaxf(fabsf(res), 1e-12f));
                float wt  = wv * hub;
                float dr0 = -sth*sxv - cth*syv;
                float dr1 =  cth*sxv - sth*syv;
                float j2  = m.z*dr0 + m.w*dr1;
                a00 = wt*m.z*m.z; a01 = wt*m.z*m.w; a02 = wt*m.z*j2;
                a11 = wt*m.w*m.w; a12 = wt*m.w*j2;  a22 = wt*j2*j2;
                g0  = wt*m.z*res; g1  = wt*m.w*res; g2  = wt*j2*res;
            }
        }

        // warp tree-reduce 9 values
        #pragma unroll
        for (int off = 16; off; off >>= 1) {
            a00 += __shfl_xor_sync(0xffffffffu, a00, off);
            a01 += __shfl_xor_sync(0xffffffffu, a01, off);
            a02 += __shfl_xor_sync(0xffffffffu, a02, off);
            a11 += __shfl_xor_sync(0xffffffffu, a11, off);
            a12 += __shfl_xor_sync(0xffffffffu, a12, off);
            a22 += __shfl_xor_sync(0xffffffffu, a22, off);
            g0  += __shfl_xor_sync(0xffffffffu, g0 , off);
            g1  += __shfl_xor_sync(0xffffffffu, g1 , off);
            g2  += __shfl_xor_sync(0xffffffffu, g2 , off);
        }
        if (lane == 0) {
            S.red[wid][0]=a00; S.red[wid][1]=a01; S.red[wid][2]=a02;
            S.red[wid][3]=a11; S.red[wid][4]=a12; S.red[wid][5]=a22;
            S.red[wid][6]=g0;  S.red[wid][7]=g1;  S.red[wid][8]=g2;
        }
        __syncthreads();

        // warp 0: reduce 16 warp partials, broadcast to all cluster CTAs
        if (wid == 0) {
            float r9[9];
            #pragma unroll
            for (int k = 0; k < 9; ++k) r9[k] = (lane < 16) ? S.red[lane][k] : 0.f;
            #pragma unroll
            for (int off = 8; off; off >>= 1) {
                #pragma unroll
                for (int k = 0; k < 9; ++k)
                    r9[k] += __shfl_xor_sync(0xffffffffu, r9[k], off);
            }
            if (lane == 0) {
                uint32_t slot = partialBase + (uint32_t)((parity*CLU + crank) * 48);
                #pragma unroll
                for (int t = 0; t < CLU; ++t) {
                    uint32_t dst = mapa_rank(slot, (uint32_t)t);
                    #pragma unroll
                    for (int k = 0; k < 9; ++k)
                        st_cluster_f32(dst + 4u*k, r9[k]);
                }
            }
        }

        cluster_sync();  // partials visible everywhere

        // every THREAD redundantly sums + solves (identical fp32 everywhere)
        {
            float4 p0a = S.partial[parity][0][0], p0b = S.partial[parity][0][1], p0c = S.partial[parity][0][2];
            float4 p1a = S.partial[parity][1][0], p1b = S.partial[parity][1][1], p1c = S.partial[parity][1][2];
            float4 p2a = S.partial[parity][2][0], p2b = S.partial[parity][2][1], p2c = S.partial[parity][2][2];
            float4 p3a = S.partial[parity][3][0], p3b = S.partial[parity][3][1], p3c = S.partial[parity][3][2];
            float r0 = p0a.x + p1a.x + p2a.x + p3a.x;
            float r1 = p0a.y + p1a.y + p2a.y + p3a.y;
            float r2 = p0a.z + p1a.z + p2a.z + p3a.z;
            float r3 = p0a.w + p1a.w + p2a.w + p3a.w;
            float r4 = p0b.x + p1b.x + p2b.x + p3b.x;
            float r5 = p0b.y + p1b.y + p2b.y + p3b.y;
            float r6 = p0b.z + p1b.z + p2b.z + p3b.z;
            float r7 = p0b.w + p1b.w + p2b.w + p3b.w;
            float r8 = p0c.x + p1c.x + p2c.x + p3c.x;
            float A00 = r0 + 1e-8f, A01 = r1, A02 = r2;
            float A11 = r3 + 1e-8f, A12 = r4, A22 = r5 + 1e-8f;
            float G0 = r6, G1 = r7, G2 = r8;
            float l00 = sqrtf(fmaxf(A00, 1e-30f));
            float l10 = A01 / l00, l20 = A02 / l00;
            float l11 = sqrtf(fmaxf(A11 - l10*l10, 1e-30f));
            float l21 = (A12 - l20*l10) / l11;
            float l22 = sqrtf(fmaxf(A22 - l20*l20 - l21*l21, 1e-30f));
            float y0 = (-G0) / l00;
            float y1 = (-G1 - l10*y0) / l11;
            float y2 = (-G2 - l20*y0 - l21*y1) / l22;
            float x2 = y2 / l22;
            float x1 = (y1 - l21*x2) / l11;
            float x0 = (y0 - l10*x1 - l20*x2) / l00;
            theta += x2;
            tx += x0;
            ty += x1;
        }
        // no trailing barrier: state is register-resident and identical
    }

    if (tid == 0 && crank == 0) {
        float c = cosf(theta), s = sinf(theta);
        float* T = out + b*16;
        T[0]=c;   T[1]=-s;  T[2]=0.f; T[3]=tx;
        T[4]=s;   T[5]=c;   T[6]=0.f; T[7]=ty;
        T[8]=0.f; T[9]=0.f; T[10]=1.f;T[11]=0.f;
        T[12]=0.f;T[13]=0.f;T[14]=0.f;T[15]=1.f;
    }
    // last DSMEM writes precede the final in-loop cluster.sync -> safe to exit
}

// NOTE: reduction layout change — partial writes use 48B stride per rank slot.
// st_cluster writes target S.partial[parity][crank] as 9 consecutive floats,
// matching the float4[3] layout read back above.

// ---------------------------------------------------------------------------
extern "C" void kernel_launch(void* const* d_in, const int* in_sizes, int n_in,
                              void* d_out, int out_size) {
    (void)in_sizes; (void)n_in; (void)out_size;
    const float* fft    = (const float*)d_in[0];
    const float* az     = (const float*)d_in[1];
    // d_in[2] = az_timestamps (unused)
    const float* map_pc = (const float*)d_in[3];
    const float* T_init = (const float*)d_in[4];
    const float* params = (const float*)d_in[5];
    float* out = (float*)d_out;

    extract_kernel<<<(B_*A_*32 + 127)/128, 128>>>(fft, az, params);

    cudaFuncSetAttribute(icp_kernel,
                         cudaFuncAttributeMaxDynamicSharedMemorySize,
                         (int)sizeof(IcpSmem));
    icp_kernel<<<B_*CLU, NTH, sizeof(IcpSmem)>>>(map_pc, T_init, out);
}